// round 4
// baseline (speedup 1.0000x reference)
#include <cuda_runtime.h>
#include <limits.h>

// Problem shape (fixed by setup_inputs): B=256, N=65536, half=32768.
#define NCOL   65536
#define HALF   32768
#define BDIM   512
#define NITER  (HALF / 4 / BDIM)      // 16
#define NSEG   256                    // segments of 128 elements per half
#define MAXB   1024

#define THRESH  0.01f
#define PENALTY 2.0f

__device__ float        g_partials[MAXB];
__device__ unsigned int g_counter = 0;

__device__ __forceinline__ unsigned long long mk_policy_evict_first() {
    unsigned long long pol;
    asm("createpolicy.fractional.L2::evict_first.b64 %0, 1.0;" : "=l"(pol));
    return pol;
}
__device__ __forceinline__ float4 ld_pol(const float4* p, unsigned long long pol) {
    float4 v;
    asm volatile("ld.global.nc.L2::cache_hint.v4.f32 {%0,%1,%2,%3}, [%4], %5;"
                 : "=f"(v.x), "=f"(v.y), "=f"(v.z), "=f"(v.w)
                 : "l"(p), "l"(pol));
    return v;
}

__device__ __forceinline__ void chk(float v, int idx, int& tmin, int& tmax) {
    if (fabsf(v) > THRESH) {
        tmin = min(tmin, idx);
        tmax = max(tmax, idx);
    }
}

__global__ __launch_bounds__(BDIM, 2)
void fused_loss_kernel(const float* __restrict__ pred,
                       const float* __restrict__ lab,
                       float* __restrict__ out,
                       int B)
{
    const int b = blockIdx.x;
    const size_t row = (size_t)b * NCOL;
    const float4* __restrict__ lr4 = (const float4*)(lab  + row);
    const float4* __restrict__ li4 = (const float4*)(lab  + row + HALF);
    const float4* __restrict__ pr4 = (const float4*)(pred + row);
    const float4* __restrict__ pi4 = (const float4*)(pred + row + HALF);

    const unsigned long long pol = mk_policy_evict_first();

    __shared__ float s_segr[NSEG];     // per-128-element-segment sum of dr^2
    __shared__ float s_segi[NSEG];     // per-segment sum of di^2
    __shared__ int   s_min_r, s_max_r, s_min_i, s_max_i;
    __shared__ bool  s_is_last;
    if (threadIdx.x == 0) {
        s_min_r = INT_MAX; s_max_r = -1;
        s_min_i = INT_MAX; s_max_i = -1;
    }
    __syncthreads();

    const int lane = threadIdx.x & 31;
    const int warp = threadIdx.x >> 5;

    // ================= SINGLE PASS =================
    // Per iteration: one float4 from each of the 4 streams; compute base loss,
    // track min/max significant label index, and warp-reduce dr^2/di^2 into a
    // per-(warp,iter) contiguous 128-element segment sum.
    int tmin_r = INT_MAX, tmax_r = -1;
    int tmin_i = INT_MAX, tmax_i = -1;
    float acc = 0.0f;

    #pragma unroll 4
    for (int it = 0; it < NITER; it++) {
        int j4 = threadIdx.x + it * BDIM;
        float4 lrv = ld_pol(lr4 + j4, pol);
        float4 liv = ld_pol(li4 + j4, pol);
        float4 prv = ld_pol(pr4 + j4, pol);
        float4 piv = ld_pol(pi4 + j4, pol);
        int base = j4 * 4;

        float sr = 0.0f, si = 0.0f;
        #pragma unroll
        for (int k = 0; k < 4; k++) {
            float lrx = (&lrv.x)[k];
            float lix = (&liv.x)[k];
            float prx = (&prv.x)[k];
            float pix = (&piv.x)[k];
            int   j   = base + k;

            chk(lrx, j, tmin_r, tmax_r);
            chk(lix, j, tmin_i, tmax_i);

            float dr   = prx - lrx;
            float di   = pix - lix;
            float dint = (prx * prx + pix * pix) - (lrx * lrx + lix * lix);

            float dr2 = dr * dr;
            float di2 = di * di;
            sr += dr2;
            si += di2;
            acc += dr2 + di2 + 50.0f * dint * dint;
        }
        // reduce this iter's dr^2 / di^2 across the warp -> segment sum
        #pragma unroll
        for (int off = 16; off > 0; off >>= 1) {
            sr += __shfl_xor_sync(0xFFFFFFFFu, sr, off);
            si += __shfl_xor_sync(0xFFFFFFFFu, si, off);
        }
        if (lane == 0) {
            int s = it * (BDIM / 32) + warp;   // segment s covers elements [128s, 128s+128)
            s_segr[s] = sr;
            s_segi[s] = si;
        }
    }

    // ---- min/max reduction ----
    #pragma unroll
    for (int off = 16; off > 0; off >>= 1) {
        tmin_r = min(tmin_r, __shfl_xor_sync(0xFFFFFFFFu, tmin_r, off));
        tmax_r = max(tmax_r, __shfl_xor_sync(0xFFFFFFFFu, tmax_r, off));
        tmin_i = min(tmin_i, __shfl_xor_sync(0xFFFFFFFFu, tmin_i, off));
        tmax_i = max(tmax_i, __shfl_xor_sync(0xFFFFFFFFu, tmax_i, off));
    }
    if (lane == 0) {
        atomicMin(&s_min_r, tmin_r);
        atomicMax(&s_max_r, tmax_r);
        atomicMin(&s_min_i, tmin_i);
        atomicMax(&s_max_i, tmax_i);
    }
    __syncthreads();   // covers segment writes + min/max

    const int fr = (s_max_r < 0) ? 0        : s_min_r;
    const int lr = (s_max_r < 0) ? HALF - 1 : s_max_r;
    const int fi = (s_max_i < 0) ? 0        : s_min_i;
    const int li = (s_max_i < 0) ? HALF - 1 : s_max_i;

    const int sfr = fr >> 7, slr = lr >> 7;
    const int sfi = fi >> 7, sli = li >> 7;

    // ---- correction: (P-1) * sum of dr^2/di^2 outside [first,last] ----
    float corr = 0.0f;
    {
        int t = threadIdx.x;
        // full segments strictly outside the boundary segments
        if (t < NSEG) {
            if (t < sfr || t > slr) corr += s_segr[t];
        } else {
            int s = t - NSEG;
            if (s < sfi || s > sli) corr += s_segi[s];
        }
        // boundary segments, element-exact (re-read ~4KB from L2)
        int grp = t >> 7;          // 0..3
        int u   = t & 127;
        int j; bool active; const float* lp; const float* pp;
        if (grp == 0)      { j = (sfr << 7) + u; active = (j < fr); lp = lab + row;        pp = pred + row;        }
        else if (grp == 1) { j = (slr << 7) + u; active = (j > lr); lp = lab + row;        pp = pred + row;        }
        else if (grp == 2) { j = (sfi << 7) + u; active = (j < fi); lp = lab + row + HALF; pp = pred + row + HALF; }
        else               { j = (sli << 7) + u; active = (j > li); lp = lab + row + HALF; pp = pred + row + HALF; }
        if (active) {
            float d = pp[j] - lp[j];
            corr += d * d;
        }
    }
    acc += (PENALTY - 1.0f) * corr;

    // ---- block sum reduction ----
    __shared__ float s_warp[BDIM / 32];
    #pragma unroll
    for (int off = 16; off > 0; off >>= 1)
        acc += __shfl_xor_sync(0xFFFFFFFFu, acc, off);
    if (lane == 0)
        s_warp[warp] = acc;
    __syncthreads();
    if (threadIdx.x < 32) {
        float v = (threadIdx.x < BDIM / 32) ? s_warp[threadIdx.x] : 0.0f;
        #pragma unroll
        for (int off = 16; off > 0; off >>= 1)
            v += __shfl_xor_sync(0xFFFFFFFFu, v, off);
        if (threadIdx.x == 0)
            g_partials[b] = v;
    }

    // ---- last CTA folds the per-row partials ----
    if (threadIdx.x == 0) {
        __threadfence();
        unsigned int ticket = atomicAdd(&g_counter, 1u);
        s_is_last = (ticket == (unsigned int)(B - 1));
    }
    __syncthreads();

    if (s_is_last) {
        __threadfence();
        __shared__ float s_fin[256];
        if (threadIdx.x < 256)
            s_fin[threadIdx.x] = (threadIdx.x < B) ? g_partials[threadIdx.x] : 0.0f;
        __syncthreads();
        #pragma unroll
        for (int st = 128; st > 0; st >>= 1) {
            if (threadIdx.x < st) s_fin[threadIdx.x] += s_fin[threadIdx.x + st];
            __syncthreads();
        }
        if (threadIdx.x == 0) {
            out[0] = s_fin[0] / ((float)HALF * (float)B);
            g_counter = 0;   // reset for graph replay
        }
    }
}

extern "C" void kernel_launch(void* const* d_in, const int* in_sizes, int n_in,
                              void* d_out, int out_size)
{
    const float* pred = (const float*)d_in[0];
    const float* lab  = (const float*)d_in[1];
    float* out = (float*)d_out;

    const int B = in_sizes[0] / NCOL;   // 256

    fused_loss_kernel<<<B, BDIM>>>(pred, lab, out, B);
}